// round 12
// baseline (speedup 1.0000x reference)
#include <cuda_runtime.h>
#include <math.h>
#include <stdint.h>
#include <stddef.h>

#define HH    65
#define HW    4225
#define BB    4
#define CIN   2048
#define INNER 256
#define NCAT  1280
#define NC    19
#define QL    2975
#define TEMPc 0.2f
#define EPSn  1e-5f

// ---------------- static device workspace (no runtime allocation) ----------------
__device__ float ws_aspp[BB * NCAT * HW];
__device__ float ws_fea [BB * INNER * HW];
__device__ float ws_gp  [BB * CIN];
__device__ float ws_z0  [BB * INNER];
__device__ float ws_br0v[BB * INNER];
__device__ float ws_gcat[4 * INNER];
__device__ float ws_bcat[4 * INNER];
__device__ float ws_mean[4 * INNER];
__device__ float ws_inv [4 * INNER];
__device__ float ws_fmean[INNER];
__device__ float ws_finv [INNER];
__device__ int   ws_pred[BB * HW];
__device__ float ws_sums[NC * INNER];
__device__ float ws_counts[NC];
__device__ float ws_keys[NC * INNER];
__device__ float ws_present[NC];
__device__ float ws_a  [NC * NC * QL];
__device__ float ws_lse[NC * NC];
__device__ float wt_1x1[CIN * INNER];
__device__ float wt_d12[9 * CIN * INNER];
__device__ float wt_d24[9 * CIN * INNER];
__device__ float wt_d36[9 * CIN * INNER];
__device__ float wt_h  [9 * NCAT * INNER];

// ---------------- block reductions (blockDim.x == 256) ----------------
__device__ __forceinline__ float blockSum(float v, float* sh) {
    __syncthreads();
    int tid = threadIdx.x;
    #pragma unroll
    for (int o = 16; o; o >>= 1) v += __shfl_down_sync(0xffffffffu, v, o);
    if ((tid & 31) == 0) sh[tid >> 5] = v;
    __syncthreads();
    if (tid < 32) {
        v = (tid < 8) ? sh[tid] : 0.f;
        #pragma unroll
        for (int o = 4; o; o >>= 1) v += __shfl_down_sync(0xffffffffu, v, o);
        if (tid == 0) sh[0] = v;
    }
    __syncthreads();
    return sh[0];
}

__device__ __forceinline__ float blockMax(float v, float* sh) {
    __syncthreads();
    int tid = threadIdx.x;
    #pragma unroll
    for (int o = 16; o; o >>= 1) v = fmaxf(v, __shfl_down_sync(0xffffffffu, v, o));
    if ((tid & 31) == 0) sh[tid >> 5] = v;
    __syncthreads();
    if (tid < 32) {
        v = (tid < 8) ? sh[tid] : -3.0e38f;
        #pragma unroll
        for (int o = 4; o; o >>= 1) v = fmaxf(v, __shfl_down_sync(0xffffffffu, v, o));
        if (tid == 0) sh[0] = v;
    }
    __syncthreads();
    return sh[0];
}

// ---------------- init ----------------
__global__ void k_init(float* out, int lossIdx) {
    int i = blockIdx.x * 256 + threadIdx.x;
    if (i < NC * INNER) ws_sums[i] = 0.f;
    if (i < NC) ws_counts[i] = 0.f;
    if (i == 0) out[lossIdx] = 0.f;
}

// ---------------- weight transposes: (co,ci[,3,3]) -> [tap][ci][co(256)] ----------------
__global__ void k_tr1(const float* __restrict__ w, float* __restrict__ wt) {
    int i = blockIdx.x * 256 + threadIdx.x;
    if (i >= CIN * INNER) return;
    int ci = i >> 8, co = i & 255;
    wt[i] = w[co * CIN + ci];
}
__global__ void k_tr3(const float* __restrict__ w, float* __restrict__ wt, int Cin) {
    int i = blockIdx.x * 256 + threadIdx.x;
    if (i >= 9 * Cin * 256) return;
    int t = i / (Cin * 256);
    int rem = i - t * Cin * 256;
    int ci = rem >> 8, co = rem & 255;
    wt[i] = w[(co * Cin + ci) * 9 + t];
}

// ---------------- global-pool branch ----------------
__global__ void k_gp(const float* __restrict__ x) {
    __shared__ float sh[32];
    int ci = blockIdx.x, b = blockIdx.y;
    const float* px = x + ((size_t)b * CIN + ci) * HW;
    float s = 0.f;
    for (int p = threadIdx.x; p < HW; p += 256) s += px[p];
    s = blockSum(s, sh);
    if (threadIdx.x == 0) ws_gp[b * CIN + ci] = s / (float)HW;
}

__global__ void k_z0(const float* __restrict__ wgp) {
    __shared__ float sh[32];
    int co = blockIdx.x, b = blockIdx.y;
    const float* w = wgp + (size_t)co * CIN;
    const float* g = ws_gp + (size_t)b * CIN;
    float s = 0.f;
    for (int ci = threadIdx.x; ci < CIN; ci += 256) s += w[ci] * g[ci];
    s = blockSum(s, sh);
    if (threadIdx.x == 0) ws_z0[b * INNER + co] = s;
}

__global__ void k_br0v(const float* __restrict__ g_gp, const float* __restrict__ b_gp) {
    int co = threadIdx.x;
    float z[BB];
    #pragma unroll
    for (int b = 0; b < BB; ++b) z[b] = ws_z0[b * INNER + co];
    float m = 0.25f * (z[0] + z[1] + z[2] + z[3]);
    float v = 0.f;
    #pragma unroll
    for (int b = 0; b < BB; ++b) { float d = z[b] - m; v += d * d; }
    v *= 0.25f;
    float inv = rsqrtf(v + EPSn);
    float gg = g_gp[co], bb = b_gp[co];
    #pragma unroll
    for (int b = 0; b < BB; ++b) {
        float y = gg * (z[b] - m) * inv + bb;
        ws_br0v[b * INNER + co] = fmaxf(y, 0.f);
    }
}

__global__ void k_fill0() {
    int idx = blockIdx.x * 256 + threadIdx.x;
    if (idx >= BB * INNER * HW) return;
    int p = idx % HW;
    int t = idx / HW;
    int c = t % INNER;
    int b = t / INNER;
    ws_aspp[((size_t)b * NCAT + c) * HW + p] = ws_br0v[b * INNER + c];
}

__global__ void k_cat(const float* g0, const float* g1, const float* g2, const float* g3,
                      const float* c0, const float* c1, const float* c2, const float* c3) {
    int i = blockIdx.x * 256 + threadIdx.x;
    if (i >= 4 * INNER) return;
    int s = i >> 8, o = i & 255;
    const float* g = (s == 0) ? g0 : (s == 1) ? g1 : (s == 2) ? g2 : g3;
    const float* c = (s == 0) ? c0 : (s == 1) ? c1 : (s == 2) ? c2 : c3;
    ws_gcat[i] = g[o];
    ws_bcat[i] = c[o];
}

// ---------------- implicit-GEMM conv: 128(co) x 64(p) tile, FFMA2 inner ----------------
__global__ void __launch_bounds__(256, 2) conv_ig(
    const float* __restrict__ in, const float* __restrict__ Wt,
    float* __restrict__ out, int Cin, int inBStride, int outBStride,
    int dil, int ntaps)
{
    __shared__ __align__(16) float As[16][128];
    __shared__ __align__(16) float Bsd[16][128];  // duplicated: Bsd[r][2j]==Bsd[r][2j+1]

    const int tid = threadIdx.x;
    const int p0 = blockIdx.x * 64;
    const int coBase = blockIdx.y * 128;
    const int b = blockIdx.z;
    in  += (size_t)b * inBStride;
    out += (size_t)b * outBStride + (size_t)coBase * HW;

    const int tx = tid & 15;        // pixel quad (4 pixels)
    const int ty = tid >> 4;        // co group (8 outputs)
    const int jcol = tid & 63;      // owned Bs pixel on load
    const int rbase = tid >> 6;     // 0..3
    const int cA = tid & 127;       // owned As column on load
    const int rAbase = tid >> 7;    // 0..1

    const int p = p0 + jcol;
    const bool pv = p < HW;
    const int y = p / HH;
    const int xpos = p - y * HH;
    const int y_lo = p0 / HH;
    const int pmax = (p0 + 63 < HW) ? (p0 + 63) : (HW - 1);
    const int y_hi = pmax / HH;

    unsigned long long acc[4][4];
    #pragma unroll
    for (int i = 0; i < 4; ++i)
        #pragma unroll
        for (int j = 0; j < 4; ++j) acc[i][j] = 0ull;

    for (int t = 0; t < ntaps; ++t) {
        int dy = 0, dx = 0;
        if (ntaps > 1) { dy = (t / 3 - 1) * dil; dx = (t % 3 - 1) * dil; }
        if (y_hi + dy < 0 || y_lo + dy >= HH) continue;   // tap dead for whole tile
        const bool ok = pv && ((unsigned)(xpos + dx) < (unsigned)HH)
                           && ((unsigned)(y + dy) < (unsigned)HH);
        const float* src = in + (ptrdiff_t)(p + dy * HH + dx);
        const float* Wtt = Wt + (size_t)t * Cin * 256;

        for (int k0 = 0; k0 < Cin; k0 += 16) {
            #pragma unroll
            for (int i = 0; i < 8; ++i)
                As[rAbase + 2 * i][cA] =
                    Wtt[(size_t)(k0 + rAbase + 2 * i) * 256 + coBase + cA];
            #pragma unroll
            for (int i = 0; i < 4; ++i) {
                int r = rbase + 4 * i;
                float v = ok ? src[(size_t)(k0 + r) * HW] : 0.f;
                unsigned long long dv;
                asm("mov.b64 %0, {%1, %1};" : "=l"(dv) : "f"(v));
                *(unsigned long long*)&Bsd[r][2 * jcol] = dv;
            }
            __syncthreads();
            #pragma unroll
            for (int kk = 0; kk < 16; ++kk) {
                ulonglong2 a01 = *(const ulonglong2*)&As[kk][ty * 8];
                ulonglong2 a23 = *(const ulonglong2*)&As[kk][ty * 8 + 4];
                ulonglong2 b01 = *(const ulonglong2*)&Bsd[kk][tx * 8];
                ulonglong2 b23 = *(const ulonglong2*)&Bsd[kk][tx * 8 + 4];
                unsigned long long av[4] = {a01.x, a01.y, a23.x, a23.y};
                unsigned long long bv[4] = {b01.x, b01.y, b23.x, b23.y};
                #pragma unroll
                for (int i = 0; i < 4; ++i)
                    #pragma unroll
                    for (int j = 0; j < 4; ++j)
                        asm("fma.rn.f32x2 %0, %1, %2, %0;"
                            : "+l"(acc[i][j]) : "l"(av[i]), "l"(bv[j]));
            }
            __syncthreads();
        }
    }

    #pragma unroll
    for (int i = 0; i < 4; ++i) {
        int co0 = ty * 8 + 2 * i;
        #pragma unroll
        for (int j = 0; j < 4; ++j) {
            int pp = p0 + tx * 4 + j;
            if (pp < HW) {
                unsigned long long v = acc[i][j];
                out[(size_t)co0 * HW + pp] =
                    __uint_as_float((unsigned)(v & 0xffffffffu));
                out[(size_t)(co0 + 1) * HW + pp] =
                    __uint_as_float((unsigned)(v >> 32));
            }
        }
    }
}

// ---------------- BN over (N,H,W): stats + apply(ReLU) ----------------
__global__ void k_bn_stats(const float* __restrict__ in, int bstride,
                           float* __restrict__ mean, float* __restrict__ inv) {
    __shared__ float sh[32];
    int c = blockIdx.x;
    const float* base = in + (size_t)c * HW;
    float s = 0.f, sq = 0.f;
    for (int b = 0; b < BB; ++b) {
        const float* pb = base + (size_t)b * bstride;
        for (int p = threadIdx.x; p < HW; p += 256) {
            float v = pb[p];
            s += v; sq += v * v;
        }
    }
    s = blockSum(s, sh);
    sq = blockSum(sq, sh);
    if (threadIdx.x == 0) {
        float m = s / (float)(BB * HW);
        float var = fmaxf(sq / (float)(BB * HW) - m * m, 0.f);
        mean[c] = m;
        inv[c] = rsqrtf(var + EPSn);
    }
}

__global__ void k_bn_apply(float* __restrict__ io, int nch, int bstride,
                           const float* __restrict__ mean, const float* __restrict__ inv,
                           const float* __restrict__ g, const float* __restrict__ beta) {
    int idx = blockIdx.x * 256 + threadIdx.x;
    if (idx >= BB * nch * HW) return;
    int p = idx % HW;
    int t = idx / HW;
    int c = t % nch;
    int b = t / nch;
    float* ptr = io + (size_t)b * bstride + (size_t)c * HW + p;
    float yv = g[c] * ((*ptr) - mean[c]) * inv[c] + beta[c];
    *ptr = fmaxf(yv, 0.f);
}

// ---------------- final 1x1 classifier + argmax ----------------
__global__ void k_final(const float* __restrict__ wfin, const float* __restrict__ bfin,
                        float* __restrict__ res) {
    __shared__ float ws[NC * INNER];
    __shared__ float bs[NC];
    int tid = threadIdx.x;
    for (int i = tid; i < NC * INNER; i += 256) ws[i] = wfin[i];
    if (tid < NC) bs[tid] = bfin[tid];
    __syncthreads();
    int b = blockIdx.y;
    int p = blockIdx.x * 256 + tid;
    if (p >= HW) return;
    const float* f = ws_fea + (size_t)b * INNER * HW + p;
    float acc[NC];
    #pragma unroll
    for (int k = 0; k < NC; ++k) acc[k] = 0.f;
    for (int c = 0; c < INNER; ++c) {
        float v = f[(size_t)c * HW];
        #pragma unroll
        for (int k = 0; k < NC; ++k) acc[k] = fmaf(v, ws[k * INNER + c], acc[k]);
    }
    float best = -3.0e38f;
    int bi = 0;
    #pragma unroll
    for (int k = 0; k < NC; ++k) {
        float r = acc[k] + bs[k];
        res[((size_t)b * NC + k) * HW + p] = r;
        if (r > best) { best = r; bi = k; }    // first-max == jnp.argmax
    }
    ws_pred[b * HW + p] = bi;
}

// ---------------- region counts / sums / keys ----------------
__global__ void k_counts() {
    __shared__ int bins[NC];
    int tid = threadIdx.x, b = blockIdx.x;
    if (tid < NC) bins[tid] = 0;
    __syncthreads();
    for (int p = tid; p < HW; p += 256) atomicAdd(&bins[ws_pred[b * HW + p]], 1);
    __syncthreads();
    if (tid < NC) atomicAdd(&ws_counts[tid], (float)bins[tid]);
}

__global__ void k_sums() {
    __shared__ float s[NC];
    int tid = threadIdx.x;
    int c = blockIdx.x, b = blockIdx.y;
    if (tid < NC) s[tid] = 0.f;
    __syncthreads();
    const float* f = ws_fea + ((size_t)b * INNER + c) * HW;
    const int* pr = ws_pred + b * HW;
    for (int p = tid; p < HW; p += 256) atomicAdd(&s[pr[p]], f[p]);
    __syncthreads();
    if (tid < NC) atomicAdd(&ws_sums[tid * INNER + c], s[tid]);
}

__global__ void k_keys() {
    __shared__ float sh[32];
    __shared__ float nrm;
    int k = blockIdx.x, c = threadIdx.x;
    float cnt = ws_counts[k];
    float v = ws_sums[k * INNER + c] / fmaxf(cnt, 1.f);
    float tot = blockSum(v * v, sh);
    if (c == 0) nrm = sqrtf(tot);
    __syncthreads();
    ws_keys[k * INNER + c] = v / fmaxf(nrm, 1e-12f);
    if (c == 0) ws_present[k] = (cnt > 0.f) ? 1.f : 0.f;
}

// ---------------- sims / logsumexp / loss ----------------
__global__ void k_sims(const float* __restrict__ queues) {
    __shared__ float ks[NC * INNER];
    int tid = threadIdx.x;
    for (int i = tid; i < NC * INNER; i += 128) ks[i] = ws_keys[i];
    __syncthreads();
    int j = blockIdx.x;
    int l = blockIdx.y * 128 + tid;
    if (l >= QL) return;
    const float* q = queues + (size_t)j * INNER * QL + l;
    float acc[NC];
    #pragma unroll
    for (int k = 0; k < NC; ++k) acc[k] = 0.f;
    for (int c = 0; c < INNER; ++c) {
        float qv = q[(size_t)c * QL];
        #pragma unroll
        for (int k = 0; k < NC; ++k) acc[k] = fmaf(ks[k * INNER + c], qv, acc[k]);
    }
    const float sc = 1.0f / ((float)INNER * TEMPc);
    #pragma unroll
    for (int k = 0; k < NC; ++k) ws_a[((size_t)k * NC + j) * QL + l] = acc[k] * sc;
}

__global__ void k_lse() {
    __shared__ float sh[32];
    int kj = blockIdx.x;
    const float* a = ws_a + (size_t)kj * QL;
    float m = -3.0e38f;
    for (int l = threadIdx.x; l < QL; l += 256) m = fmaxf(m, a[l]);
    m = blockMax(m, sh);
    float s = 0.f;
    for (int l = threadIdx.x; l < QL; l += 256) s += expf(a[l] - m);
    s = blockSum(s, sh);
    if (threadIdx.x == 0) ws_lse[kj] = m + logf(s);
}

__global__ void k_loss(float* out, int lossIdx) {
    __shared__ float sh[32];
    int k = blockIdx.x;
    float m = -3.0e38f;
    for (int j = 0; j < NC; ++j) if (j != k) m = fmaxf(m, ws_lse[k * NC + j]);
    float s = 0.f;
    for (int j = 0; j < NC; ++j) if (j != k) s += expf(ws_lse[k * NC + j] - m);
    float lneg = m + logf(s);
    const float* pos = ws_a + ((size_t)k * NC + k) * QL;
    float acc = 0.f;
    for (int l = threadIdx.x; l < QL; l += 256) {
        float p = pos[l];
        float mm = fmaxf(p, lneg);
        acc += mm + log1pf(expf(fminf(p, lneg) - mm)) - p;
    }
    acc = blockSum(acc, sh);
    if (threadIdx.x == 0) atomicAdd(out + lossIdx, ws_present[k] * acc / (float)QL);
}

// ---------------- launcher ----------------
extern "C" void kernel_launch(void* const* d_in, const int* in_sizes, int n_in,
                              void* d_out, int out_size) {
    const float* x      = (const float*)d_in[0];
    const float* w_gp   = (const float*)d_in[1];
    const float* g_gp   = (const float*)d_in[2];
    const float* b_gp   = (const float*)d_in[3];
    const float* w_1x1  = (const float*)d_in[4];
    const float* g_1x1  = (const float*)d_in[5];
    const float* b_1x1  = (const float*)d_in[6];
    const float* w_d12  = (const float*)d_in[7];
    const float* g_d12  = (const float*)d_in[8];
    const float* b_d12  = (const float*)d_in[9];
    const float* w_d24  = (const float*)d_in[10];
    const float* g_d24  = (const float*)d_in[11];
    const float* b_d24  = (const float*)d_in[12];
    const float* w_d36  = (const float*)d_in[13];
    const float* g_d36  = (const float*)d_in[14];
    const float* b_d36  = (const float*)d_in[15];
    const float* w_head = (const float*)d_in[16];
    const float* g_head = (const float*)d_in[17];
    const float* b_head = (const float*)d_in[18];
    const float* w_fin  = (const float*)d_in[19];
    const float* b_fin  = (const float*)d_in[20];
    const float* queues = (const float*)d_in[21];
    float* out = (float*)d_out;
    const int lossIdx = out_size - 1;

    float *p_aspp, *p_fea, *p_mean, *p_inv, *p_gcat, *p_bcat, *p_fmean, *p_finv;
    float *p_w1, *p_w12, *p_w24, *p_w36, *p_wh;
    cudaGetSymbolAddress((void**)&p_aspp, ws_aspp);
    cudaGetSymbolAddress((void**)&p_fea, ws_fea);
    cudaGetSymbolAddress((void**)&p_mean, ws_mean);
    cudaGetSymbolAddress((void**)&p_inv, ws_inv);
    cudaGetSymbolAddress((void**)&p_gcat, ws_gcat);
    cudaGetSymbolAddress((void**)&p_bcat, ws_bcat);
    cudaGetSymbolAddress((void**)&p_fmean, ws_fmean);
    cudaGetSymbolAddress((void**)&p_finv, ws_finv);
    cudaGetSymbolAddress((void**)&p_w1, wt_1x1);
    cudaGetSymbolAddress((void**)&p_w12, wt_d12);
    cudaGetSymbolAddress((void**)&p_w24, wt_d24);
    cudaGetSymbolAddress((void**)&p_w36, wt_d36);
    cudaGetSymbolAddress((void**)&p_wh, wt_h);

    k_init<<<19, 256>>>(out, lossIdx);

    // weight transposes
    k_tr1<<<(CIN * INNER + 255) / 256, 256>>>(w_1x1, p_w1);
    k_tr3<<<(9 * CIN * 256 + 255) / 256, 256>>>(w_d12, p_w12, CIN);
    k_tr3<<<(9 * CIN * 256 + 255) / 256, 256>>>(w_d24, p_w24, CIN);
    k_tr3<<<(9 * CIN * 256 + 255) / 256, 256>>>(w_d36, p_w36, CIN);
    k_tr3<<<(9 * NCAT * 256 + 255) / 256, 256>>>(w_head, p_wh, NCAT);

    // global-pool branch
    k_gp<<<dim3(CIN, BB), 256>>>(x);
    k_z0<<<dim3(INNER, BB), 256>>>(w_gp);
    k_br0v<<<1, 256>>>(g_gp, b_gp);
    k_fill0<<<(BB * INNER * HW + 255) / 256, 256>>>();

    // convs into concat buffer (un-normalized), channel offsets 1..4
    dim3 cgrid((HW + 63) / 64, 2, BB);
    conv_ig<<<cgrid, 256>>>(x, p_w1,  p_aspp + (size_t)1 * INNER * HW, CIN,
                            CIN * HW, NCAT * HW, 1, 1);
    conv_ig<<<cgrid, 256>>>(x, p_w12, p_aspp + (size_t)2 * INNER * HW, CIN,
                            CIN * HW, NCAT * HW, 12, 9);
    conv_ig<<<cgrid, 256>>>(x, p_w24, p_aspp + (size_t)3 * INNER * HW, CIN,
                            CIN * HW, NCAT * HW, 24, 9);
    conv_ig<<<cgrid, 256>>>(x, p_w36, p_aspp + (size_t)4 * INNER * HW, CIN,
                            CIN * HW, NCAT * HW, 36, 9);

    // per-branch BN + ReLU (branches 1..4, 1024 channels)
    k_cat<<<4, 256>>>(g_1x1, g_d12, g_d24, g_d36, b_1x1, b_d12, b_d24, b_d36);
    k_bn_stats<<<4 * INNER, 256>>>(p_aspp + (size_t)INNER * HW, NCAT * HW, p_mean, p_inv);
    k_bn_apply<<<(BB * 4 * INNER * HW + 255) / 256, 256>>>(
        p_aspp + (size_t)INNER * HW, 4 * INNER, NCAT * HW, p_mean, p_inv, p_gcat, p_bcat);

    // head conv + BN + ReLU
    conv_ig<<<cgrid, 256>>>(p_aspp, p_wh, p_fea, NCAT, NCAT * HW, INNER * HW, 1, 9);
    k_bn_stats<<<INNER, 256>>>(p_fea, INNER * HW, p_fmean, p_finv);
    k_bn_apply<<<(BB * INNER * HW + 255) / 256, 256>>>(
        p_fea, INNER, INNER * HW, p_fmean, p_finv, g_head, b_head);

    // final classifier + argmax
    k_final<<<dim3((HW + 255) / 256, BB), 256>>>(w_fin, b_fin, out);

    // region keys
    k_counts<<<BB, 256>>>();
    k_sums<<<dim3(INNER, BB), 256>>>();
    k_keys<<<NC, 256>>>();

    // contrast loss
    k_sims<<<dim3(NC, (QL + 127) / 128), 128>>>(queues);
    k_lse<<<NC * NC, 256>>>();
    k_loss<<<NC, 256>>>(out, lossIdx);
}

// round 15
// speedup vs baseline: 4.7981x; 4.7981x over previous
#include <cuda_runtime.h>
#include <cuda_bf16.h>
#include <math.h>
#include <stdint.h>
#include <stddef.h>

#define HH    65
#define HW    4225
#define BB    4
#define CIN   2048
#define INNER 256
#define NCAT  1280
#define NC    19
#define QL    2975
#define TEMPc 0.2f
#define EPSn  1e-5f

__device__ float ws_aspp[BB * NCAT * HW];
__device__ float ws_fea [BB * INNER * HW];
__device__ float ws_gp  [BB * CIN];
__device__ float ws_z0  [BB * INNER];
__device__ float ws_br0v[BB * INNER];
__device__ float ws_gcat[4 * INNER];
__device__ float ws_bcat[4 * INNER];
__device__ float ws_mean[4 * INNER];
__device__ float ws_inv [4 * INNER];
__device__ float ws_fmean[INNER];
__device__ float ws_finv [INNER];
__device__ int   ws_pred[BB * HW];
__device__ float ws_sums[NC * INNER];
__device__ float ws_counts[NC];
__device__ float ws_keys[NC * INNER];
__device__ float ws_present[NC];
__device__ float ws_a  [NC * NC * QL];
__device__ float ws_lse[NC * NC];

__device__ __align__(128) __nv_bfloat16 xT_h[(size_t)BB * HW * CIN];
__device__ __align__(128) __nv_bfloat16 xT_l[(size_t)BB * HW * CIN];
__device__ __align__(128) __nv_bfloat16 aT_h[(size_t)BB * HW * NCAT];
__device__ __align__(128) __nv_bfloat16 aT_l[(size_t)BB * HW * NCAT];
__device__ __align__(128) __nv_bfloat16 pk1 [(size_t)1 * 2 * 32 * 2 * 8192];
__device__ __align__(128) __nv_bfloat16 pk12[(size_t)9 * 2 * 32 * 2 * 8192];
__device__ __align__(128) __nv_bfloat16 pk24[(size_t)9 * 2 * 32 * 2 * 8192];
__device__ __align__(128) __nv_bfloat16 pk36[(size_t)9 * 2 * 32 * 2 * 8192];
__device__ __align__(128) __nv_bfloat16 pkh [(size_t)9 * 2 * 20 * 2 * 8192];

#define SWZ(b) ((unsigned)(b) ^ ((((unsigned)(b)) >> 3) & 0x70u))

#define LDSM4(r, a) asm volatile( \
    "ldmatrix.sync.aligned.m8n8.x4.shared.b16 {%0,%1,%2,%3}, [%4];" \
    : "=r"((r)[0]), "=r"((r)[1]), "=r"((r)[2]), "=r"((r)[3]) : "r"(a))
#define LDSM2(r, a) asm volatile( \
    "ldmatrix.sync.aligned.m8n8.x2.shared.b16 {%0,%1}, [%2];" \
    : "=r"((r)[0]), "=r"((r)[1]) : "r"(a))
#define MMA(d, a, bq) asm volatile( \
    "mma.sync.aligned.m16n8k16.row.col.f32.bf16.bf16.f32 " \
    "{%0,%1,%2,%3}, {%4,%5,%6,%7}, {%8,%9}, {%0,%1,%2,%3};" \
    : "+f"((d)[0]), "+f"((d)[1]), "+f"((d)[2]), "+f"((d)[3]) \
    : "r"((a)[0]), "r"((a)[1]), "r"((a)[2]), "r"((a)[3]), \
      "r"((bq)[0]), "r"((bq)[1]))

static __device__ __forceinline__ void cpa16(unsigned d, const void* s) {
    asm volatile("cp.async.cg.shared.global [%0], [%1], 16;"
                 :: "r"(d), "l"(s) : "memory");
}
static __device__ __forceinline__ void cpa16z(unsigned d, const void* s, int sz) {
    asm volatile("cp.async.cg.shared.global [%0], [%1], 16, %2;"
                 :: "r"(d), "l"(s), "r"(sz) : "memory");
}

__device__ __forceinline__ float blockSum(float v, float* sh) {
    __syncthreads();
    int tid = threadIdx.x;
    #pragma unroll
    for (int o = 16; o; o >>= 1) v += __shfl_down_sync(0xffffffffu, v, o);
    if ((tid & 31) == 0) sh[tid >> 5] = v;
    __syncthreads();
    if (tid < 32) {
        v = (tid < 8) ? sh[tid] : 0.f;
        #pragma unroll
        for (int o = 4; o; o >>= 1) v += __shfl_down_sync(0xffffffffu, v, o);
        if (tid == 0) sh[0] = v;
    }
    __syncthreads();
    return sh[0];
}
__device__ __forceinline__ float blockMax(float v, float* sh) {
    __syncthreads();
    int tid = threadIdx.x;
    #pragma unroll
    for (int o = 16; o; o >>= 1) v = fmaxf(v, __shfl_down_sync(0xffffffffu, v, o));
    if ((tid & 31) == 0) sh[tid >> 5] = v;
    __syncthreads();
    if (tid < 32) {
        v = (tid < 8) ? sh[tid] : -3.0e38f;
        #pragma unroll
        for (int o = 4; o; o >>= 1) v = fmaxf(v, __shfl_down_sync(0xffffffffu, v, o));
        if (tid == 0) sh[0] = v;
    }
    __syncthreads();
    return sh[0];
}

__global__ void k_init(float* out, int lossIdx) {
    int i = blockIdx.x * 256 + threadIdx.x;
    if (i < NC * INNER) ws_sums[i] = 0.f;
    if (i < NC) ws_counts[i] = 0.f;
    if (i == 0) out[lossIdx] = 0.f;
}

// transpose+split x: [b][c][p] -> [b][p][c] bf16 hi/lo
__global__ void k_xt(const float* __restrict__ src, __nv_bfloat16* __restrict__ th,
                     __nv_bfloat16* __restrict__ tl, int Cin) {
    __shared__ float t[32][33];
    int b = blockIdx.z, p0 = blockIdx.x * 32, c0 = blockIdx.y * 32;
    int lx = threadIdx.x, ly = threadIdx.y;
    const float* s = src + ((size_t)b * Cin + c0) * HW + p0;
    for (int j = ly; j < 32; j += 8)
        t[j][lx] = (p0 + lx < HW) ? s[(size_t)j * HW + lx] : 0.f;
    __syncthreads();
    for (int j = ly; j < 32; j += 8) {
        int pp = p0 + j;
        if (pp >= HW) continue;
        float v = t[lx][j];
        __nv_bfloat16 h = __float2bfloat16(v);
        size_t idx = ((size_t)b * HW + pp) * Cin + c0 + lx;
        th[idx] = h;
        tl[idx] = __float2bfloat16(v - __bfloat162float(h));
    }
}

// weight pack (OIHW) -> [tap][cb][kc][hi|lo][8192 swizzled]
__global__ void k_wpack(const float* __restrict__ w, __nv_bfloat16* __restrict__ pk,
                        int Cin, int taps) {
    size_t i = (size_t)blockIdx.x * 256 + threadIdx.x;
    if (i >= (size_t)taps * Cin * 256) return;
    int col = (int)(i & 63);
    size_t r1 = i >> 6;
    int row = (int)(r1 & 127); r1 >>= 7;
    int KC = Cin >> 6;
    int kc = (int)(r1 % KC); r1 /= KC;
    int cbv = (int)(r1 & 1);
    int t = (int)(r1 >> 1);
    int co = cbv * 128 + row, ci = kc * 64 + col;
    float v = w[((size_t)co * Cin + ci) * taps + t];
    __nv_bfloat16 h = __float2bfloat16(v);
    unsigned sw = SWZ(row * 128 + col * 2) >> 1;
    size_t tb = ((((size_t)t * 2 + cbv) * KC + kc) * 2) * 8192;
    pk[tb + sw] = h;
    pk[tb + 8192 + sw] = __float2bfloat16(v - __bfloat162float(h));
}

__global__ void k_gp(const float* __restrict__ x) {
    __shared__ float sh[32];
    int ci = blockIdx.x, b = blockIdx.y;
    const float* px = x + ((size_t)b * CIN + ci) * HW;
    float s = 0.f;
    for (int p = threadIdx.x; p < HW; p += 256) s += px[p];
    s = blockSum(s, sh);
    if (threadIdx.x == 0) ws_gp[b * CIN + ci] = s / (float)HW;
}
__global__ void k_z0(const float* __restrict__ wgp) {
    __shared__ float sh[32];
    int co = blockIdx.x, b = blockIdx.y;
    const float* w = wgp + (size_t)co * CIN;
    const float* g = ws_gp + (size_t)b * CIN;
    float s = 0.f;
    for (int ci = threadIdx.x; ci < CIN; ci += 256) s += w[ci] * g[ci];
    s = blockSum(s, sh);
    if (threadIdx.x == 0) ws_z0[b * INNER + co] = s;
}
__global__ void k_br0v(const float* __restrict__ g_gp, const float* __restrict__ b_gp) {
    int co = threadIdx.x;
    float z[BB];
    #pragma unroll
    for (int b = 0; b < BB; ++b) z[b] = ws_z0[b * INNER + co];
    float m = 0.25f * (z[0] + z[1] + z[2] + z[3]);
    float v = 0.f;
    #pragma unroll
    for (int b = 0; b < BB; ++b) { float d = z[b] - m; v += d * d; }
    float inv = rsqrtf(v * 0.25f + EPSn);
    float gg = g_gp[co], bb = b_gp[co];
    #pragma unroll
    for (int b = 0; b < BB; ++b)
        ws_br0v[b * INNER + co] = fmaxf(gg * (z[b] - m) * inv + bb, 0.f);
}
__global__ void k_fill0T() {
    size_t idx = (size_t)blockIdx.x * 256 + threadIdx.x;
    if (idx >= (size_t)BB * HW * 256) return;
    int c = (int)(idx & 255);
    size_t t = idx >> 8;
    int p = (int)(t % HW);
    int b = (int)(t / HW);
    float v = ws_br0v[b * 256 + c];
    __nv_bfloat16 h = __float2bfloat16(v);
    size_t o = ((size_t)b * HW + p) * NCAT + c;
    aT_h[o] = h;
    aT_l[o] = __float2bfloat16(v - __bfloat162float(h));
}
__global__ void k_cat(const float* g0, const float* g1, const float* g2, const float* g3,
                      const float* c0, const float* c1, const float* c2, const float* c3) {
    int i = blockIdx.x * 256 + threadIdx.x;
    if (i >= 4 * INNER) return;
    int s = i >> 8, o = i & 255;
    const float* g = (s == 0) ? g0 : (s == 1) ? g1 : (s == 2) ? g2 : g3;
    const float* c = (s == 0) ? c0 : (s == 1) ? c1 : (s == 2) ? c2 : c3;
    ws_gcat[i] = g[o];
    ws_bcat[i] = c[o];
}
// fused BN+ReLU+transpose+split for concat branches 1..4
__global__ void k_bnT() {
    __shared__ float t[32][33];
    int b = blockIdx.z, p0 = blockIdx.x * 32, c0 = blockIdx.y * 32;
    int lx = threadIdx.x, ly = threadIdx.y;
    const float* s = ws_aspp + ((size_t)b * NCAT + 256 + c0) * HW + p0;
    for (int j = ly; j < 32; j += 8)
        t[j][lx] = (p0 + lx < HW) ? s[(size_t)j * HW + lx] : 0.f;
    __syncthreads();
    int c = c0 + lx;
    float mn = ws_mean[c], iv = ws_inv[c], gg = ws_gcat[c], bb = ws_bcat[c];
    for (int j = ly; j < 32; j += 8) {
        int pp = p0 + j;
        if (pp >= HW) continue;
        float v = fmaxf(gg * (t[lx][j] - mn) * iv + bb, 0.f);
        __nv_bfloat16 h = __float2bfloat16(v);
        size_t o = ((size_t)b * HW + pp) * NCAT + 256 + c;
        aT_h[o] = h;
        aT_l[o] = __float2bfloat16(v - __bfloat162float(h));
    }
}

// mma.sync conv: 128co x 64px CTA tile, split-bf16 3-term, cp.async double buffer
// stage layout: A_hi[0,16K) A_lo[16K,32K) B_hi[32K,40K) B_lo[40K,48K); 2 stages
__global__ void __launch_bounds__(256, 2) conv_mm(
    const __nv_bfloat16* __restrict__ xTh, const __nv_bfloat16* __restrict__ xTl,
    const __nv_bfloat16* __restrict__ wp, float* __restrict__ out,
    int Cin, int outBStride, int dil, int ntaps)
{
    extern __shared__ __align__(128) char smem[];
    unsigned sb = (unsigned)__cvta_generic_to_shared(smem);
    const int tid = threadIdx.x;
    const int lane = tid & 31, wid = tid >> 5;
    const int pbase = blockIdx.x * 64;
    const int cb = blockIdx.y, b = blockIdx.z;
    const int KC = Cin >> 6;

    const __nv_bfloat16* xb_h = xTh + (size_t)b * HW * Cin;
    const __nv_bfloat16* xb_l = xTl + (size_t)b * HW * Cin;

    const int ylo = pbase / HH;
    const int pmaxv = (pbase + 63 < HW) ? pbase + 63 : HW - 1;
    const int yhi = pmaxv / HH;

    int tlist[9], nt = 0;
    for (int t = 0; t < ntaps; ++t) {
        int dy = (ntaps > 1) ? (t / 3 - 1) * dil : 0;
        if (yhi + dy >= 0 && ylo + dy < HH) tlist[nt++] = t;
    }
    const int total = nt * KC;

    const int r0 = tid >> 3;          // B row pair: r0, r0+32
    const int c8 = (tid & 7) * 8;     // ci offset within 64

    auto stageLoad = [&](int idx, int s) {
        int tt = tlist[idx / KC];
        int kc = idx - (idx / KC) * KC;
        int dy = 0, dx = 0;
        if (ntaps > 1) { dy = (tt / 3 - 1) * dil; dx = (tt % 3 - 1) * dil; }
        unsigned st = sb + s * 49152;
        const uint4* sa = (const uint4*)(wp +
            (((size_t)tt * 2 + cb) * KC + kc) * 2 * 8192);
        #pragma unroll
        for (int i = 0; i < 8; ++i)
            cpa16(st + (tid + 256 * i) * 16, sa + tid + 256 * i);
        #pragma unroll
        for (int rr = 0; rr < 2; ++rr) {
            int pg = pbase + r0 + rr * 32;
            int yy = pg / HH, xx = pg - yy * HH;
            bool ok = (pg < HW) && ((unsigned)(yy + dy) < (unsigned)HH)
                                && ((unsigned)(xx + dx) < (unsigned)HH);
            size_t off = ok ? ((size_t)(pg + dy * HH + dx) * Cin + kc * 64 + c8) : 0;
            int sz = ok ? 16 : 0;
            unsigned so = SWZ((r0 + rr * 32) * 128 + (tid & 7) * 16);
            cpa16z(st + 32768 + so, xb_h + off, sz);
            cpa16z(st + 40960 + so, xb_l + off, sz);
        }
        asm volatile("cp.async.commit_group;" ::: "memory");
    };

    const int mrow = (wid & 3) * 32;
    const int ncol = (wid >> 2) * 32;
    float acc[2][4][4];
    #pragma unroll
    for (int mi = 0; mi < 2; ++mi)
        #pragma unroll
        for (int ni = 0; ni < 4; ++ni)
            #pragma unroll
            for (int r = 0; r < 4; ++r) acc[mi][ni][r] = 0.f;

    if (total > 0) {
        stageLoad(0, 0);
        for (int i = 0; i < total; ++i) {
            asm volatile("cp.async.wait_group 0;" ::: "memory");
            __syncthreads();
            if (i + 1 < total) stageLoad(i + 1, (i + 1) & 1);
            unsigned st = sb + (i & 1) * 49152;
            #pragma unroll
            for (int ks = 0; ks < 4; ++ks) {
                int k0 = ks * 16;
                unsigned ah[2][4], al[2][4];
                #pragma unroll
                for (int mi = 0; mi < 2; ++mi) {
                    int row = mrow + mi * 16 + (lane & 15);
                    int col = k0 + (lane >> 4) * 8;
                    unsigned ad = st + SWZ(row * 128 + col * 2);
                    LDSM4(ah[mi], ad);
                    LDSM4(al[mi], ad + 16384);
                }
                unsigned bh[4][2], bl[4][2];
                #pragma unroll
                for (int ni = 0; ni < 4; ++ni) {
                    int rowp = ncol + ni * 8 + (lane & 7);
                    int col = k0 + ((lane >> 3) & 1) * 8;
                    unsigned bd = st + 32768 + SWZ(rowp * 128 + col * 2);
                    LDSM2(bh[ni], bd);
                    LDSM2(bl[ni], bd + 8192);
                }
                #pragma unroll
                for (int mi = 0; mi < 2; ++mi)
                    #pragma unroll
                    for (int ni = 0; ni < 4; ++ni) {
                        MMA(acc[mi][ni], ah[mi], bh[ni]);
                        MMA(acc[mi][ni], ah[mi], bl[ni]);
                        MMA(acc[mi][ni], al[mi], bh[ni]);
                    }
            }
            __syncthreads();
        }
    }

    float* ob = out + (size_t)b * outBStride + (size_t)(cb * 128) * HW;
    #pragma unroll
    for (int mi = 0; mi < 2; ++mi)
        #pragma unroll
        for (int ni = 0; ni < 4; ++ni)
            #pragma unroll
            for (int r = 0; r < 4; ++r) {
                int co = mrow + mi * 16 + (lane >> 2) + (r >> 1) * 8;
                int px = pbase + ncol + ni * 8 + (lane & 3) * 2 + (r & 1);
                if (px < HW) ob[(size_t)co * HW + px] = acc[mi][ni][r];
            }
}

__global__ void k_bn_stats(const float* __restrict__ in, int bstride,
                           float* __restrict__ mean, float* __restrict__ inv) {
    __shared__ float sh[32];
    int c = blockIdx.x;
    const float* base = in + (size_t)c * HW;
    float s = 0.f, sq = 0.f;
    for (int b = 0; b < BB; ++b) {
        const float* pb = base + (size_t)b * bstride;
        for (int p = threadIdx.x; p < HW; p += 256) {
            float v = pb[p];
            s += v; sq += v * v;
        }
    }
    s = blockSum(s, sh);
    sq = blockSum(sq, sh);
    if (threadIdx.x == 0) {
        float m = s / (float)(BB * HW);
        mean[c] = m;
        inv[c] = rsqrtf(fmaxf(sq / (float)(BB * HW) - m * m, 0.f) + EPSn);
    }
}
__global__ void k_bn_apply(float* __restrict__ io, int nch, int bstride,
                           const float* __restrict__ mean, const float* __restrict__ inv,
                           const float* __restrict__ g, const float* __restrict__ beta) {
    int idx = blockIdx.x * 256 + threadIdx.x;
    if (idx >= BB * nch * HW) return;
    int p = idx % HW;
    int t = idx / HW;
    int c = t % nch;
    int b = t / nch;
    float* ptr = io + (size_t)b * bstride + (size_t)c * HW + p;
    *ptr = fmaxf(g[c] * ((*ptr) - mean[c]) * inv[c] + beta[c], 0.f);
}

__global__ void k_final(const float* __restrict__ wfin, const float* __restrict__ bfin,
                        float* __restrict__ res) {
    __shared__ float ws[NC * INNER];
    __shared__ float bs[NC];
    int tid = threadIdx.x;
    for (int i = tid; i < NC * INNER; i += 256) ws[i] = wfin[i];
    if (tid < NC) bs[tid] = bfin[tid];
    __syncthreads();
    int b = blockIdx.y;
    int p = blockIdx.x * 256 + tid;
    if (p >= HW) return;
    const float* f = ws_fea + (size_t)b * INNER * HW + p;
    float acc[NC];
    #pragma unroll
    for (int k = 0; k < NC; ++k) acc[k] = 0.f;
    for (int c = 0; c < INNER; ++c) {
        float v = f[(size_t)c * HW];
        #pragma unroll
        for (int k = 0; k < NC; ++k) acc[k] = fmaf(v, ws[k * INNER + c], acc[k]);
    }
    float best = -3.0e38f;
    int bi = 0;
    #pragma unroll
    for (int k = 0; k < NC; ++k) {
        float r = acc[k] + bs[k];
        res[((size_t)b * NC + k) * HW + p] = r;
        if (r > best) { best = r; bi = k; }
    }
    ws_pred[b * HW + p] = bi;
}

__global__ void k_counts() {
    __shared__ int bins[NC];
    int tid = threadIdx.x, b = blockIdx.x;
    if (tid < NC) bins[tid] = 0;
    __syncthreads();
    for (int p = tid; p < HW; p += 256) atomicAdd(&bins[ws_pred[b * HW + p]], 1);
    __syncthreads();
    if (tid < NC) atomicAdd(&ws_counts[tid], (float)bins[tid]);
}
__global__ void k_sums() {
    __shared__ float s[NC];
    int tid = threadIdx.x;
    int c = blockIdx.x, b = blockIdx.y;
    if (tid < NC) s[tid] = 0.f;
    __syncthreads();
    const float* f = ws_fea + ((size_t)b * INNER + c) * HW;
    const int* pr = ws_pred + b * HW;
    for (int p = tid; p < HW; p += 256) atomicAdd(&s[pr[p]], f[p]);
    __syncthreads();
    if (tid < NC) atomicAdd(&ws_sums[tid * INNER + c], s[tid]);
}
__global__ void k_keys() {
    __shared__ float sh[32];
    __shared__ float nrm;
    int k = blockIdx.x, c = threadIdx.x;
    float cnt = ws_counts[k];
    float v = ws_sums[k * INNER + c] / fmaxf(cnt, 1.f);
    float tot = blockSum(v * v, sh);
    if (c == 0) nrm = sqrtf(tot);
    __syncthreads();
    ws_keys[k * INNER + c] = v / fmaxf(nrm, 1e-12f);
    if (c == 0) ws_present[k] = (cnt > 0.f) ? 1.f : 0.f;
}
__global__ void k_sims(const float* __restrict__ queues) {
    __shared__ float ks[NC * INNER];
    int tid = threadIdx.x;
    for (int i = tid; i < NC * INNER; i += 128) ks[i] = ws_keys[i];
    __syncthreads();
    int j = blockIdx.x;
    int l = blockIdx.y * 128 + tid;
    if (l >= QL) return;
    const float* q = queues + (size_t)j * INNER * QL + l;
    float acc[NC];
    #pragma unroll
    for (int k = 0; k < NC; ++k) acc[k] = 0.f;
    for (int c = 0; c < INNER; ++c) {
        float qv = q[(size_t)c * QL];
        #pragma unroll
        for (int k = 0; k < NC; ++k) acc[k] = fmaf(ks[k * INNER + c], qv, acc[k]);
    }
    const float sc = 1.0f / ((float)INNER * TEMPc);
    #pragma unroll
    for (int k = 0; k < NC; ++k) ws_a[((size_t)k * NC + j) * QL + l] = acc[k] * sc;
}
__global__ void k_lse() {
    __shared__ float sh[32];
    int kj = blockIdx.x;
    const float* a = ws_a + (size_t)kj * QL;
    float m = -3.0e38f;
    for (int l = threadIdx.x; l < QL; l += 256) m = fmaxf(m, a[l]);
    m = blockMax(m, sh);
    float s = 0.f;
    for (int l = threadIdx.x; l < QL; l += 256) s += expf(a[l] - m);
    s = blockSum(s, sh);
    if (threadIdx.x == 0) ws_lse[kj] = m + logf(s);
}
__global__ void k_loss(float* out, int lossIdx) {
    __shared__ float sh[32];
    int k = blockIdx.x;
    float m = -3.0e38f;
    for (int j = 0; j < NC; ++j) if (j != k) m = fmaxf(m, ws_lse[k * NC + j]);
    float s = 0.f;
    for (int j = 0; j < NC; ++j) if (j != k) s += expf(ws_lse[k * NC + j] - m);
    float lneg = m + logf(s);
    const float* pos = ws_a + ((size_t)k * NC + k) * QL;
    float acc = 0.f;
    for (int l = threadIdx.x; l < QL; l += 256) {
        float p = pos[l];
        float mm = fmaxf(p, lneg);
        acc += mm + log1pf(expf(fminf(p, lneg) - mm)) - p;
    }
    acc = blockSum(acc, sh);
    if (threadIdx.x == 0) atomicAdd(out + lossIdx, ws_present[k] * acc / (float)QL);
}

extern "C" void kernel_launch(void* const* d_in, const int* in_sizes, int n_in,
                              void* d_out, int out_size) {
    const float* x      = (const float*)d_in[0];
    const float* w_gp   = (const float*)d_in[1];
    const float* g_gp   = (const float*)d_in[2];
    const float* b_gp   = (const float*)d_in[3];
    const float* w_1x1  = (const float*)d_in[4];
    const float* g_1x1  = (const float*)d_in[5];
    const float* b_1x1  = (const float*)d_in[6];
    const float* w_d12  = (const float*)d_in[7];
    const float* g_d12  = (const float*)d_in[8];
    const float* b_d12  = (const float*)d_in[9];
    const float* w_d24  = (const float*)d_in[10];
    const float* g_d24  = (const float*)d_in[11];
    const float* b_d24  = (const float*)d_in[12];
    const float* w_d36  = (const float*)d_in[13];
    const float* g_d36  = (const float*)d_in[14];
    const float* b_d36  = (const float*)d_in[15];
    const float* w_head = (const float*)d_in[16];
    const float* g_head = (const float*)d_in[17];
    const float* b_head = (const float*)d_in[18];
    const float* w_fin  = (const float*)d_in[19];
    const float* b_fin  = (const float*)d_in[20];
    const float* queues = (const float*)d_in[21];
    float* out = (float*)d_out;
    const int lossIdx = out_size - 1;

    float *p_aspp, *p_fea, *p_mean, *p_inv, *p_fmean, *p_finv;
    __nv_bfloat16 *pxh, *pxl, *pah, *pal, *q1, *q12, *q24, *q36, *qh;
    cudaGetSymbolAddress((void**)&p_aspp, ws_aspp);
    cudaGetSymbolAddress((void**)&p_fea, ws_fea);
    cudaGetSymbolAddress((void**)&p_mean, ws_mean);
    cudaGetSymbolAddress((void**)&p_inv, ws_inv);
    cudaGetSymbolAddress((void**)&p_fmean, ws_fmean);
    cudaGetSymbolAddress((void**)&p_finv, ws_finv);
    cudaGetSymbolAddress((void**)&pxh, xT_h);
    cudaGetSymbolAddress((void**)&pxl, xT_l);
    cudaGetSymbolAddress((void**)&pah, aT_h);
    cudaGetSymbolAddress((void**)&pal, aT_l);
    cudaGetSymbolAddress((void**)&q1, pk1);
    cudaGetSymbolAddress((void**)&q12, pk12);
    cudaGetSymbolAddress((void**)&q24, pk24);
    cudaGetSymbolAddress((void**)&q36, pk36);
    cudaGetSymbolAddress((void**)&qh, pkh);

    cudaFuncSetAttribute(conv_mm, cudaFuncAttributeMaxDynamicSharedMemorySize, 98304);

    k_init<<<19, 256>>>(out, lossIdx);
    k_xt<<<dim3((HW + 31) / 32, CIN / 32, BB), dim3(32, 8)>>>(x, pxh, pxl, CIN);
    k_wpack<<<(int)(((size_t)1 * CIN * 256 + 255) / 256), 256>>>(w_1x1, q1, CIN, 1);
    k_wpack<<<(int)(((size_t)9 * CIN * 256 + 255) / 256), 256>>>(w_d12, q12, CIN, 9);
    k_wpack<<<(int)(((size_t)9 * CIN * 256 + 255) / 256), 256>>>(w_d24, q24, CIN, 9);
    k_wpack<<<(int)(((size_t)9 * CIN * 256 + 255) / 256), 256>>>(w_d36, q36, CIN, 9);
    k_wpack<<<(int)(((size_t)9 * NCAT * 256 + 255) / 256), 256>>>(w_head, qh, NCAT, 9);

    k_gp<<<dim3(CIN, BB), 256>>>(x);
    k_z0<<<dim3(INNER, BB), 256>>>(w_gp);
    k_br0v<<<1, 256>>>(g_gp, b_gp);
    k_fill0T<<<(int)(((size_t)BB * HW * 256 + 255) / 256), 256>>>();

    dim3 cgrid((HW + 63) / 64, 2, BB);
    conv_mm<<<cgrid, 256, 98304>>>(pxh, pxl, q1,  p_aspp + (size_t)1 * INNER * HW,
                                   CIN, NCAT * HW, 1, 1);
    conv_mm<<<cgrid, 256, 98304>>>(pxh, pxl, q12, p_aspp + (size_t)2 * INNER * HW,
                                   CIN, NCAT * HW, 12, 9);
    conv_mm<<<cgrid, 256, 98304>>>(pxh, pxl, q24, p_aspp + (size_t)3 * INNER * HW,
                                   CIN, NCAT * HW, 24, 9);
    conv_mm<<<cgrid, 256, 98304>>>(pxh, pxl, q36, p_aspp + (size_t)4 * INNER * HW,
                                   CIN, NCAT * HW, 36, 9);

    k_cat<<<4, 256>>>(g_1x1, g_d12, g_d24, g_d36, b_1x1, b_d12, b_d24, b_d36);
    k_bn_stats<<<4 * INNER, 256>>>(p_aspp + (size_t)INNER * HW, NCAT * HW, p_mean, p_inv);
    k_bnT<<<dim3((HW + 31) / 32, 1024 / 32, BB), dim3(32, 8)>>>();

    conv_mm<<<cgrid, 256, 98304>>>(pah, pal, qh, p_fea, NCAT, INNER * HW, 1, 9);
    k_bn_stats<<<INNER, 256>>>(p_fea, INNER * HW, p_fmean, p_finv);
    k_bn_apply<<<(BB * INNER * HW + 255) / 256, 256>>>(
        p_fea, INNER, INNER * HW, p_fmean, p_finv, g_head, b_head);

    k_final<<<dim3((HW + 255) / 256, BB), 256>>>(w_fin, b_fin, out);
    k_counts<<<BB, 256>>>();
    k_sums<<<dim3(INNER, BB), 256>>>();
    k_keys<<<NC, 256>>>();
    k_sims<<<dim3(NC, (QL + 127) / 128), 128>>>(queues);
    k_lse<<<NC * NC, 256>>>();
    k_loss<<<NC, 256>>>(out, lossIdx);
}

// round 17
// speedup vs baseline: 4.8713x; 1.0153x over previous
#include <cuda_runtime.h>
#include <cuda_bf16.h>
#include <math.h>
#include <stdint.h>
#include <stddef.h>

#define HH    65
#define HW    4225
#define BB    4
#define CIN   2048
#define INNER 256
#define NCAT  1280
#define NC    19
#define QL    2975
#define TEMPc 0.2f
#define EPSn  1e-5f

__device__ float ws_aspp[BB * NCAT * HW];
__device__ float ws_fea [BB * INNER * HW];
__device__ float ws_gp  [BB * CIN];
__device__ float ws_z0  [BB * INNER];
__device__ float ws_br0v[BB * INNER];
__device__ float ws_gcat[4 * INNER];
__device__ float ws_bcat[4 * INNER];
__device__ float ws_mean[4 * INNER];
__device__ float ws_inv [4 * INNER];
__device__ float ws_fmean[INNER];
__device__ float ws_finv [INNER];
__device__ int   ws_pred[BB * HW];
__device__ float ws_sums[NC * INNER];
__device__ float ws_counts[NC];
__device__ float ws_keys[NC * INNER];
__device__ float ws_present[NC];
__device__ float ws_a  [NC * NC * QL];
__device__ float ws_lse[NC * NC];

__device__ __align__(128) __nv_bfloat16 xT_h[(size_t)BB * HW * CIN];
__device__ __align__(128) __nv_bfloat16 xT_l[(size_t)BB * HW * CIN];
__device__ __align__(128) __nv_bfloat16 aT_h[(size_t)BB * HW * NCAT];
__device__ __align__(128) __nv_bfloat16 aT_l[(size_t)BB * HW * NCAT];
__device__ __align__(128) __nv_bfloat16 pk1 [(size_t)1 * 2 * 32 * 2 * 8192];
__device__ __align__(128) __nv_bfloat16 pk12[(size_t)9 * 2 * 32 * 2 * 8192];
__device__ __align__(128) __nv_bfloat16 pk24[(size_t)9 * 2 * 32 * 2 * 8192];
__device__ __align__(128) __nv_bfloat16 pk36[(size_t)9 * 2 * 32 * 2 * 8192];
__device__ __align__(128) __nv_bfloat16 pkh [(size_t)9 * 2 * 20 * 2 * 8192];

#define SWZ(b) ((unsigned)(b) ^ ((((unsigned)(b)) >> 3) & 0x70u))

#define LDSM4(r, a) asm volatile( \
    "ldmatrix.sync.aligned.m8n8.x4.shared.b16 {%0,%1,%2,%3}, [%4];" \
    : "=r"((r)[0]), "=r"((r)[1]), "=r"((r)[2]), "=r"((r)[3]) : "r"(a))
#define LDSM2(r, a) asm volatile( \
    "ldmatrix.sync.aligned.m8n8.x2.shared.b16 {%0,%1}, [%2];" \
    : "=r"((r)[0]), "=r"((r)[1]) : "r"(a))
#define MMA(d, a, bq) asm volatile( \
    "mma.sync.aligned.m16n8k16.row.col.f32.bf16.bf16.f32 " \
    "{%0,%1,%2,%3}, {%4,%5,%6,%7}, {%8,%9}, {%0,%1,%2,%3};" \
    : "+f"((d)[0]), "+f"((d)[1]), "+f"((d)[2]), "+f"((d)[3]) \
    : "r"((a)[0]), "r"((a)[1]), "r"((a)[2]), "r"((a)[3]), \
      "r"((bq)[0]), "r"((bq)[1]))

static __device__ __forceinline__ void cpa16(unsigned d, const void* s) {
    asm volatile("cp.async.cg.shared.global [%0], [%1], 16;"
                 :: "r"(d), "l"(s) : "memory");
}
static __device__ __forceinline__ void cpa16z(unsigned d, const void* s, int sz) {
    asm volatile("cp.async.cg.shared.global [%0], [%1], 16, %2;"
                 :: "r"(d), "l"(s), "r"(sz) : "memory");
}

__device__ __forceinline__ float blockSum(float v, float* sh) {
    __syncthreads();
    int tid = threadIdx.x;
    #pragma unroll
    for (int o = 16; o; o >>= 1) v += __shfl_down_sync(0xffffffffu, v, o);
    if ((tid & 31) == 0) sh[tid >> 5] = v;
    __syncthreads();
    if (tid < 32) {
        v = (tid < 8) ? sh[tid] : 0.f;
        #pragma unroll
        for (int o = 4; o; o >>= 1) v += __shfl_down_sync(0xffffffffu, v, o);
        if (tid == 0) sh[0] = v;
    }
    __syncthreads();
    return sh[0];
}
__device__ __forceinline__ float blockMax(float v, float* sh) {
    __syncthreads();
    int tid = threadIdx.x;
    #pragma unroll
    for (int o = 16; o; o >>= 1) v = fmaxf(v, __shfl_down_sync(0xffffffffu, v, o));
    if ((tid & 31) == 0) sh[tid >> 5] = v;
    __syncthreads();
    if (tid < 32) {
        v = (tid < 8) ? sh[tid] : -3.0e38f;
        #pragma unroll
        for (int o = 4; o; o >>= 1) v = fmaxf(v, __shfl_down_sync(0xffffffffu, v, o));
        if (tid == 0) sh[0] = v;
    }
    __syncthreads();
    return sh[0];
}

__global__ void k_init(float* out, int lossIdx) {
    int i = blockIdx.x * 256 + threadIdx.x;
    if (i < NC * INNER) ws_sums[i] = 0.f;
    if (i < NC) ws_counts[i] = 0.f;
    if (i == 0) out[lossIdx] = 0.f;
}

// transpose+split: [b][c][p] -> [b][p][c] bf16 hi/lo
__global__ void k_xt(const float* __restrict__ src, __nv_bfloat16* __restrict__ th,
                     __nv_bfloat16* __restrict__ tl, int Cin) {
    __shared__ float t[32][33];
    int b = blockIdx.z, p0 = blockIdx.x * 32, c0 = blockIdx.y * 32;
    int lx = threadIdx.x, ly = threadIdx.y;
    const float* s = src + ((size_t)b * Cin + c0) * HW + p0;
    for (int j = ly; j < 32; j += 8)
        t[j][lx] = (p0 + lx < HW) ? s[(size_t)j * HW + lx] : 0.f;
    __syncthreads();
    for (int j = ly; j < 32; j += 8) {
        int pp = p0 + j;
        if (pp >= HW) continue;
        float v = t[lx][j];
        __nv_bfloat16 h = __float2bfloat16(v);
        size_t idx = ((size_t)b * HW + pp) * Cin + c0 + lx;
        th[idx] = h;
        tl[idx] = __float2bfloat16(v - __bfloat162float(h));
    }
}

// weight pack (OIHW) -> [tap][cb][kc][hi|lo][8192 swizzled]
__global__ void k_wpack(const float* __restrict__ w, __nv_bfloat16* __restrict__ pk,
                        int Cin, int taps) {
    size_t i = (size_t)blockIdx.x * 256 + threadIdx.x;
    if (i >= (size_t)taps * Cin * 256) return;
    int col = (int)(i & 63);
    size_t r1 = i >> 6;
    int row = (int)(r1 & 127); r1 >>= 7;
    int KC = Cin >> 6;
    int kc = (int)(r1 % KC); r1 /= KC;
    int cbv = (int)(r1 & 1);
    int t = (int)(r1 >> 1);
    int co = cbv * 128 + row, ci = kc * 64 + col;
    float v = w[((size_t)co * Cin + ci) * taps + t];
    __nv_bfloat16 h = __float2bfloat16(v);
    unsigned sw = SWZ(row * 128 + col * 2) >> 1;
    size_t tb = ((((size_t)t * 2 + cbv) * KC + kc) * 2) * 8192;
    pk[tb + sw] = h;
    pk[tb + 8192 + sw] = __float2bfloat16(v - __bfloat162float(h));
}

__global__ void k_gp(const float* __restrict__ x) {
    __shared__ float sh[32];
    int ci = blockIdx.x, b = blockIdx.y;
    const float* px = x + ((size_t)b * CIN + ci) * HW;
    float s = 0.f;
    for (int p = threadIdx.x; p < HW; p += 256) s += px[p];
    s = blockSum(s, sh);
    if (threadIdx.x == 0) ws_gp[b * CIN + ci] = s / (float)HW;
}
__global__ void k_z0(const float* __restrict__ wgp) {
    __shared__ float sh[32];
    int co = blockIdx.x, b = blockIdx.y;
    const float* w = wgp + (size_t)co * CIN;
    const float* g = ws_gp + (size_t)b * CIN;
    float s = 0.f;
    for (int ci = threadIdx.x; ci < CIN; ci += 256) s += w[ci] * g[ci];
    s = blockSum(s, sh);
    if (threadIdx.x == 0) ws_z0[b * INNER + co] = s;
}
__global__ void k_br0v(const float* __restrict__ g_gp, const float* __restrict__ b_gp) {
    int co = threadIdx.x;
    float z[BB];
    #pragma unroll
    for (int b = 0; b < BB; ++b) z[b] = ws_z0[b * INNER + co];
    float m = 0.25f * (z[0] + z[1] + z[2] + z[3]);
    float v = 0.f;
    #pragma unroll
    for (int b = 0; b < BB; ++b) { float d = z[b] - m; v += d * d; }
    float inv = rsqrtf(v * 0.25f + EPSn);
    float gg = g_gp[co], bb = b_gp[co];
    #pragma unroll
    for (int b = 0; b < BB; ++b)
        ws_br0v[b * INNER + co] = fmaxf(gg * (z[b] - m) * inv + bb, 0.f);
}
__global__ void k_fill0T() {
    size_t idx = (size_t)blockIdx.x * 256 + threadIdx.x;
    if (idx >= (size_t)BB * HW * 256) return;
    int c = (int)(idx & 255);
    size_t t = idx >> 8;
    int p = (int)(t % HW);
    int b = (int)(t / HW);
    float v = ws_br0v[b * 256 + c];
    __nv_bfloat16 h = __float2bfloat16(v);
    size_t o = ((size_t)b * HW + p) * NCAT + c;
    aT_h[o] = h;
    aT_l[o] = __float2bfloat16(v - __bfloat162float(h));
}
__global__ void k_cat(const float* g0, const float* g1, const float* g2, const float* g3,
                      const float* c0, const float* c1, const float* c2, const float* c3) {
    int i = blockIdx.x * 256 + threadIdx.x;
    if (i >= 4 * INNER) return;
    int s = i >> 8, o = i & 255;
    const float* g = (s == 0) ? g0 : (s == 1) ? g1 : (s == 2) ? g2 : g3;
    const float* c = (s == 0) ? c0 : (s == 1) ? c1 : (s == 2) ? c2 : c3;
    ws_gcat[i] = g[o];
    ws_bcat[i] = c[o];
}
__global__ void k_bnT() {
    __shared__ float t[32][33];
    int b = blockIdx.z, p0 = blockIdx.x * 32, c0 = blockIdx.y * 32;
    int lx = threadIdx.x, ly = threadIdx.y;
    const float* s = ws_aspp + ((size_t)b * NCAT + 256 + c0) * HW + p0;
    for (int j = ly; j < 32; j += 8)
        t[j][lx] = (p0 + lx < HW) ? s[(size_t)j * HW + lx] : 0.f;
    __syncthreads();
    int c = c0 + lx;
    float mn = ws_mean[c], iv = ws_inv[c], gg = ws_gcat[c], bb = ws_bcat[c];
    for (int j = ly; j < 32; j += 8) {
        int pp = p0 + j;
        if (pp >= HW) continue;
        float v = fmaxf(gg * (t[lx][j] - mn) * iv + bb, 0.f);
        __nv_bfloat16 h = __float2bfloat16(v);
        size_t o = ((size_t)b * HW + pp) * NCAT + 256 + c;
        aT_h[o] = h;
        aT_l[o] = __float2bfloat16(v - __bfloat162float(h));
    }
}

// ---- conv core: 128co x 128px CTA tile, split-bf16 3-term, cp.async dbl-buffer ----
// stage (64KB): A_hi[0,16K) A_lo[16K,32K) B_hi[32K,48K) B_lo[48K,64K); 2 stages.
__device__ __forceinline__ void conv_core(
    const __nv_bfloat16* __restrict__ xb_h, const __nv_bfloat16* __restrict__ xb_l,
    const __nv_bfloat16* __restrict__ wp, float* __restrict__ ob,
    int Cin, int dil, int ntaps, int pbase, int cb)
{
    extern __shared__ __align__(128) char smem[];
    unsigned sb = (unsigned)__cvta_generic_to_shared(smem);
    const int tid = threadIdx.x;
    const int lane = tid & 31, wid = tid >> 5;
    const int KC = Cin >> 6;

    const int ylo = pbase / HH;
    const int pmaxv = (pbase + 127 < HW) ? pbase + 127 : HW - 1;
    const int yhi = pmaxv / HH;

    int tlist[9], nt = 0;
    for (int t = 0; t < ntaps; ++t) {
        int dy = (ntaps > 1) ? (t / 3 - 1) * dil : 0;
        if (yhi + dy >= 0 && ylo + dy < HH) tlist[nt++] = t;
    }
    const int total = nt * KC;

    const int r0 = tid >> 1;          // B row 0..127
    const int seg = tid & 1;          // ci half (32 ci = 64B)

    auto stageLoad = [&](int idx, int s) {
        int tt = tlist[idx / KC];
        int kc = idx - (idx / KC) * KC;
        int dy = 0, dx = 0;
        if (ntaps > 1) { dy = (tt / 3 - 1) * dil; dx = (tt % 3 - 1) * dil; }
        unsigned st = sb + s * 65536;
        const uint4* sa = (const uint4*)(wp +
            (((size_t)tt * 2 + cb) * KC + kc) * 2 * 8192);
        #pragma unroll
        for (int i = 0; i < 8; ++i)
            cpa16(st + (tid + 256 * i) * 16, sa + tid + 256 * i);
        int pg = pbase + r0;
        int yy = pg / HH, xx = pg - yy * HH;
        bool ok = (pg < HW) && ((unsigned)(yy + dy) < (unsigned)HH)
                            && ((unsigned)(xx + dx) < (unsigned)HH);
        size_t off = ok ? ((size_t)(pg + dy * HH + dx) * Cin + kc * 64 + seg * 32) : 0;
        int sz = ok ? 16 : 0;
        #pragma unroll
        for (int j = 0; j < 4; ++j) {
            unsigned so = SWZ(r0 * 128 + seg * 64 + j * 16);
            cpa16z(st + 32768 + so, xb_h + off + j * 8, sz);
            cpa16z(st + 49152 + so, xb_l + off + j * 8, sz);
        }
        asm volatile("cp.async.commit_group;" ::: "memory");
    };

    const int mrow = (wid & 3) * 32;
    const int ncol = (wid >> 2) * 64;
    float acc[2][8][4];
    #pragma unroll
    for (int mi = 0; mi < 2; ++mi)
        #pragma unroll
        for (int ni = 0; ni < 8; ++ni)
            #pragma unroll
            for (int r = 0; r < 4; ++r) acc[mi][ni][r] = 0.f;

    if (total > 0) {
        stageLoad(0, 0);
        for (int i = 0; i < total; ++i) {
            asm volatile("cp.async.wait_group 0;" ::: "memory");
            __syncthreads();
            if (i + 1 < total) stageLoad(i + 1, (i + 1) & 1);
            unsigned st = sb + (i & 1) * 65536;
            #pragma unroll
            for (int ks = 0; ks < 4; ++ks) {
                int k0 = ks * 16;
                unsigned ah[2][4], al[2][4];
                #pragma unroll
                for (int mi = 0; mi < 2; ++mi) {
                    int row = mrow + mi * 16 + (lane & 15);
                    int col = k0 + (lane >> 4) * 8;
                    unsigned ad = st + SWZ(row * 128 + col * 2);
                    LDSM4(ah[mi], ad);
                    LDSM4(al[mi], ad + 16384);
                }
                unsigned bh[8][2], bl[8][2];
                #pragma unroll
                for (int ni = 0; ni < 8; ++ni) {
                    int rowp = ncol + ni * 8 + (lane & 7);
                    int col = k0 + ((lane >> 3) & 1) * 8;
                    unsigned bd = st + 32768 + SWZ(rowp * 128 + col * 2);
                    LDSM2(bh[ni], bd);
                    LDSM2(bl[ni], bd + 16384);
                }
                #pragma unroll
                for (int mi = 0; mi < 2; ++mi)
                    #pragma unroll
                    for (int ni = 0; ni < 8; ++ni) {
                        MMA(acc[mi][ni], ah[mi], bh[ni]);
                        MMA(acc[mi][ni], ah[mi], bl[ni]);
                        MMA(acc[mi][ni], al[mi], bh[ni]);
                    }
            }
            __syncthreads();
        }
    }

    #pragma unroll
    for (int mi = 0; mi < 2; ++mi)
        #pragma unroll
        for (int ni = 0; ni < 8; ++ni)
            #pragma unroll
            for (int r = 0; r < 4; ++r) {
                int co = mrow + mi * 16 + (lane >> 2) + (r >> 1) * 8;
                int px = pbase + ncol + ni * 8 + (lane & 3) * 2 + (r & 1);
                if (px < HW) ob[(size_t)co * HW + px] = acc[mi][ni][r];
            }
}

// merged 4-branch ASPP conv: blockIdx.y = br*2 + cb
__global__ void __launch_bounds__(256, 1) conv_aspp(
    const __nv_bfloat16* __restrict__ xh, const __nv_bfloat16* __restrict__ xl,
    const __nv_bfloat16* __restrict__ w0, const __nv_bfloat16* __restrict__ w1,
    const __nv_bfloat16* __restrict__ w2, const __nv_bfloat16* __restrict__ w3)
{
    int byc = blockIdx.y, br = byc >> 1, cb = byc & 1, b = blockIdx.z;
    const __nv_bfloat16* wp = (br == 0) ? w0 : (br == 1) ? w1 : (br == 2) ? w2 : w3;
    int dil = (br == 0) ? 1 : (br == 1) ? 12 : (br == 2) ? 24 : 36;
    int ntaps = (br == 0) ? 1 : 9;
    float* ob = ws_aspp + (size_t)b * NCAT * HW + (size_t)((1 + br) * INNER + cb * 128) * HW;
    conv_core(xh + (size_t)b * HW * CIN, xl + (size_t)b * HW * CIN,
              wp, ob, CIN, dil, ntaps, blockIdx.x * 128, cb);
}
__global__ void __launch_bounds__(256, 1) conv_head(
    const __nv_bfloat16* __restrict__ xh, const __nv_bfloat16* __restrict__ xl,
    const __nv_bfloat16* __restrict__ wp)
{
    int cb = blockIdx.y, b = blockIdx.z;
    float* ob = ws_fea + (size_t)b * INNER * HW + (size_t)(cb * 128) * HW;
    conv_core(xh + (size_t)b * HW * NCAT, xl + (size_t)b * HW * NCAT,
              wp, ob, NCAT, 1, 9, blockIdx.x * 128, cb);
}

__global__ void k_bn_stats(const float* __restrict__ in, int bstride,
                           float* __restrict__ mean, float* __restrict__ inv) {
    __shared__ float sh[32];
    int c = blockIdx.x;
    const float* base = in + (size_t)c * HW;
    float s = 0.f, sq = 0.f;
    for (int b = 0; b < BB; ++b) {
        const float* pb = base + (size_t)b * bstride;
        for (int p = threadIdx.x; p < HW; p += 256) {
            float v = pb[p];
            s += v; sq += v * v;
        }
    }
    s = blockSum(s, sh);
    sq = blockSum(sq, sh);
    if (threadIdx.x == 0) {
        float m = s / (float)(BB * HW);
        mean[c] = m;
        inv[c] = rsqrtf(fmaxf(sq / (float)(BB * HW) - m * m, 0.f) + EPSn);
    }
}
__global__ void k_bn_apply(float* __restrict__ io, int nch, int bstride,
                           const float* __restrict__ mean, const float* __restrict__ inv,
                           const float* __restrict__ g, const float* __restrict__ beta) {
    int idx = blockIdx.x * 256 + threadIdx.x;
    if (idx >= BB * nch * HW) return;
    int p = idx % HW;
    int t = idx / HW;
    int c = t % nch;
    int b = t / nch;
    float* ptr = io + (size_t)b * bstride + (size_t)c * HW + p;
    *ptr = fmaxf(g[c] * ((*ptr) - mean[c]) * inv[c] + beta[c], 0.f);
}

__global__ void k_final(const float* __restrict__ wfin, const float* __restrict__ bfin,
                        float* __restrict__ res) {
    __shared__ float ws[NC * INNER];
    __shared__ float bs[NC];
    int tid = threadIdx.x;
    for (int i = tid; i < NC * INNER; i += 256) ws[i] = wfin[i];
    if (tid < NC) bs[tid] = bfin[tid];
    __syncthreads();
    int b = blockIdx.y;
    int p = blockIdx.x * 256 + tid;
    if (p >= HW) return;
    const float* f = ws_fea + (size_t)b * INNER * HW + p;
    float acc[NC];
    #pragma unroll
    for (int k = 0; k < NC; ++k) acc[k] = 0.f;
    for (int c = 0; c < INNER; ++c) {
        float v = f[(size_t)c * HW];
        #pragma unroll
        for (int k = 0; k < NC; ++k) acc[k] = fmaf(v, ws[k * INNER + c], acc[k]);
    }
    float best = -3.0e38f;
    int bi = 0;
    #pragma unroll
    for (int k = 0; k < NC; ++k) {
        float r = acc[k] + bs[k];
        res[((size_t)b * NC + k) * HW + p] = r;
        if (r > best) { best = r; bi = k; }
    }
    ws_pred[b * HW + p] = bi;
}

__global__ void k_counts() {
    __shared__ int bins[NC];
    int tid = threadIdx.x, b = blockIdx.x;
    if (tid < NC) bins[tid] = 0;
    __syncthreads();
    for (int p = tid; p < HW; p += 256) atomicAdd(&bins[ws_pred[b * HW + p]], 1);
    __syncthreads();
    if (tid < NC) atomicAdd(&ws_counts[tid], (float)bins[tid]);
}
__global__ void k_sums() {
    __shared__ float s[NC];
    int tid = threadIdx.x;
    int c = blockIdx.x, b = blockIdx.y;
    if (tid < NC) s[tid] = 0.f;
    __syncthreads();
    const float* f = ws_fea + ((size_t)b * INNER + c) * HW;
    const int* pr = ws_pred + b * HW;
    for (int p = tid; p < HW; p += 256) atomicAdd(&s[pr[p]], f[p]);
    __syncthreads();
    if (tid < NC) atomicAdd(&ws_sums[tid * INNER + c], s[tid]);
}
__global__ void k_keys() {
    __shared__ float sh[32];
    __shared__ float nrm;
    int k = blockIdx.x, c = threadIdx.x;
    float cnt = ws_counts[k];
    float v = ws_sums[k * INNER + c] / fmaxf(cnt, 1.f);
    float tot = blockSum(v * v, sh);
    if (c == 0) nrm = sqrtf(tot);
    __syncthreads();
    ws_keys[k * INNER + c] = v / fmaxf(nrm, 1e-12f);
    if (c == 0) ws_present[k] = (cnt > 0.f) ? 1.f : 0.f;
}
__global__ void k_sims(const float* __restrict__ queues) {
    __shared__ float ks[NC * INNER];
    int tid = threadIdx.x;
    for (int i = tid; i < NC * INNER; i += 128) ks[i] = ws_keys[i];
    __syncthreads();
    int j = blockIdx.x;
    int l = blockIdx.y * 128 + tid;
    if (l >= QL) return;
    const float* q = queues + (size_t)j * INNER * QL + l;
    float acc[NC];
    #pragma unroll
    for (int k = 0; k < NC; ++k) acc[k] = 0.f;
    for (int c = 0; c < INNER; ++c) {
        float qv = q[(size_t)c * QL];
        #pragma unroll
        for (int k = 0; k < NC; ++k) acc[k] = fmaf(ks[k * INNER + c], qv, acc[k]);
    }
    const float sc = 1.0f / ((float)INNER * TEMPc);
    #pragma unroll
    for (int k = 0; k < NC; ++k) ws_a[((size_t)k * NC + j) * QL + l] = acc[k] * sc;
}
__global__ void k_lse() {
    __shared__ float sh[32];
    int kj = blockIdx.x;
    const float* a = ws_a + (size_t)kj * QL;
    float m = -3.0e38f;
    for (int l = threadIdx.x; l < QL; l += 256) m = fmaxf(m, a[l]);
    m = blockMax(m, sh);
    float s = 0.f;
    for (int l = threadIdx.x; l < QL; l += 256) s += expf(a[l] - m);
    s = blockSum(s, sh);
    if (threadIdx.x == 0) ws_lse[kj] = m + logf(s);
}
__global__ void k_loss(float* out, int lossIdx) {
    __shared__ float sh[32];
    int k = blockIdx.x;
    float m = -3.0e38f;
    for (int j = 0; j < NC; ++j) if (j != k) m = fmaxf(m, ws_lse[k * NC + j]);
    float s = 0.f;
    for (int j = 0; j < NC; ++j) if (j != k) s += expf(ws_lse[k * NC + j] - m);
    float lneg = m + logf(s);
    const float* pos = ws_a + ((size_t)k * NC + k) * QL;
    float acc = 0.f;
    for (int l = threadIdx.x; l < QL; l += 256) {
        float p = pos[l];
        float mm = fmaxf(p, lneg);
        acc += mm + log1pf(expf(fminf(p, lneg) - mm)) - p;
    }
    acc = blockSum(acc, sh);
    if (threadIdx.x == 0) atomicAdd(out + lossIdx, ws_present[k] * acc / (float)QL);
}

extern "C" void kernel_launch(void* const* d_in, const int* in_sizes, int n_in,
                              void* d_out, int out_size) {
    const float* x      = (const float*)d_in[0];
    const float* w_gp   = (const float*)d_in[1];
    const float* g_gp   = (const float*)d_in[2];
    const float* b_gp   = (const float*)d_in[3];
    const float* w_1x1  = (const float*)d_in[4];
    const float* g_1x1  = (const float*)d_in[5];
    const float* b_1x1  = (const float*)d_in[6];
    const float* w_d12  = (const float*)d_in[7];
    const float* g_d12  = (const float*)d_in[8];
    const float* b_d12  = (const float*)d_in[9];
    const float* w_d24  = (const float*)d_in[10];
    const float* g_d24  = (const float*)d_in[11];
    const float* b_d24  = (const float*)d_in[12];
    const float* w_d36  = (const float*)d_in[13];
    const float* g_d36  = (const float*)d_in[14];
    const float* b_d36  = (const float*)d_in[15];
    const float* w_head = (const float*)d_in[16];
    const float* g_head = (const float*)d_in[17];
    const float* b_head = (const float*)d_in[18];
    const float* w_fin  = (const float*)d_in[19];
    const float* b_fin  = (const float*)d_in[20];
    const float* queues = (const float*)d_in[21];
    float* out = (float*)d_out;
    const int lossIdx = out_size - 1;

    float *p_aspp, *p_fea, *p_mean, *p_inv, *p_fmean, *p_finv;
    __nv_bfloat16 *pxh, *pxl, *pah, *pal, *q1, *q12, *q24, *q36, *qh;
    cudaGetSymbolAddress((void**)&p_aspp, ws_aspp);
    cudaGetSymbolAddress((void**)&p_fea, ws_fea);
    cudaGetSymbolAddress((void**)&p_mean, ws_mean);
    cudaGetSymbolAddress((void**)&p_inv, ws_inv);
    cudaGetSymbolAddress((void**)&p_fmean, ws_fmean);
    cudaGetSymbolAddress((void**)&p_finv, ws_finv);
    cudaGetSymbolAddress((void**)&pxh, xT_h);
    cudaGetSymbolAddress((void**)&pxl, xT_l);
    cudaGetSymbolAddress((void**)&pah, aT_h);
    cudaGetSymbolAddress((void**)&pal, aT_l);
    cudaGetSymbolAddress((void**)&q1, pk1);
    cudaGetSymbolAddress((void**)&q12, pk12);
    cudaGetSymbolAddress((void**)&q24, pk24);
    cudaGetSymbolAddress((void**)&q36, pk36);
    cudaGetSymbolAddress((void**)&qh, pkh);

    cudaFuncSetAttribute(conv_aspp, cudaFuncAttributeMaxDynamicSharedMemorySize, 131072);
    cudaFuncSetAttribute(conv_head, cudaFuncAttributeMaxDynamicSharedMemorySize, 131072);

    k_init<<<19, 256>>>(out, lossIdx);
    k_xt<<<dim3((HW + 31) / 32, CIN / 32, BB), dim3(32, 8)>>>(x, pxh, pxl, CIN);
    k_wpack<<<(int)(((size_t)1 * CIN * 256 + 255) / 256), 256>>>(w_1x1, q1, CIN, 1);
    k_wpack<<<(int)(((size_t)9 * CIN * 256 + 255) / 256), 256>>>(w_d12, q12, CIN, 9);
    k_wpack<<<(int)(((size_t)9 * CIN * 256 + 255) / 256), 256>>>(w_d24, q24, CIN, 9);
    k_wpack<<<(int)(((size_t)9 * CIN * 256 + 255) / 256), 256>>>(w_d36, q36, CIN, 9);
    k_wpack<<<(int)(((size_t)9 * NCAT * 256 + 255) / 256), 256>>>(w_head, qh, NCAT, 9);

    k_gp<<<dim3(CIN, BB), 256>>>(x);
    k_z0<<<dim3(INNER, BB), 256>>>(w_gp);
    k_br0v<<<1, 256>>>(g_gp, b_gp);
    k_fill0T<<<(int)(((size_t)BB * HW * 256 + 255) / 256), 256>>>();

    conv_aspp<<<dim3((HW + 127) / 128, 8, BB), 256, 131072>>>(pxh, pxl, q1, q12, q24, q36);

    k_cat<<<4, 256>>>(g_1x1, g_d12, g_d24, g_d36, b_1x1, b_d12, b_d24, b_d36);
    k_bn_stats<<<4 * INNER, 256>>>(p_aspp + (size_t)INNER * HW, NCAT * HW, p_mean, p_inv);
    k_bnT<<<dim3((HW + 31) / 32, 1024 / 32, BB), dim3(32, 8)>>>();

    conv_head<<<dim3((HW + 127) / 128, 2, BB), 256, 131072>>>(pah, pal, qh);
    k_bn_stats<<<INNER, 256>>>(p_fea, INNER * HW, p_fmean, p_finv);
    k_bn_apply<<<(BB * INNER * HW + 255) / 256, 256>>>(
        p_fea, INNER, INNER * HW, p_fmean, p_finv, g_head, b_head);

    k_final<<<dim3((HW + 255) / 256, BB), 256>>>(w_fin, b_fin, out);
    k_counts<<<BB, 256>>>();
    k_sums<<<dim3(INNER, BB), 256>>>();
    k_keys<<<NC, 256>>>();
    k_sims<<<dim3(NC, (QL + 127) / 128), 128>>>(queues);
    k_lse<<<NC * NC, 256>>>();
    k_loss<<<NC, 256>>>(out, lossIdx);
}